// round 15
// baseline (speedup 1.0000x reference)
#include <cuda_runtime.h>
#include <cuda_fp16.h>
#include <cstdint>

#define TT 4096
#define DD 2048
#define HH 8192
#define NE 8
#define RRK 16
#define ER 128
#define SCAL 2.0f

#define BM 128
#define BN 128
#define BK 64                  // 64 halfs of K per tile
#define NS 3
#define RS 36                  // smem row stride in words (144 B) — LDS & ldmatrix conflict-free
#define ROWB 144
#define TILEB (BM * RS * 4)    // 18432 B per operand tile
#define SMEMSZ (NS * 2 * TILEB) // 110592 B -> 2 CTAs/SM
#define NTHR 128               // 4 warps (2x2 of 64x64)

#define SPLIT1 4
#define SPLIT2 8
#define SPLITF 4               // fc2 split-K factor

// ---------------- scratch (device globals) ------------------------------------
__device__ __half g_W1h[(size_t)HH * DD];
__device__ __half g_W2h[(size_t)DD * HH];
__device__ __half g_B1h[(size_t)NE * HH * RRK];
__device__ __half g_B2h[(size_t)NE * DD * RRK];
__device__ __half g_A1h[(size_t)ER * DD];
__device__ __half g_A2h[(size_t)ER * HH];
__device__ __half g_Xh [(size_t)TT * DD];
__device__ __half g_Yh [(size_t)TT * HH];
__device__ __half g_Z1h[TT * ER];
__device__ __half g_Z2h[TT * ER];
__device__ float  g_part[(size_t)SPLITF * TT * DD];  // split-K partial slab (fc2 & Z)

// ---------------- helpers ------------------------------------------------------
__device__ __forceinline__ void cp16(uint32_t s, const void* g) {
    asm volatile("cp.async.cg.shared.global [%0], [%1], 16;" :: "r"(s), "l"(g));
}
__device__ __forceinline__ float gelu_new_f(float x) {
    float u = 0.7978845608028654f * x * (1.0f + 0.044715f * x * x);
    float e = __expf(2.0f * u);
    float t = 1.0f - 2.0f / (e + 1.0f);          // tanh(u), inf-safe
    return 0.5f * x * (1.0f + t);
}
__device__ __forceinline__ void mma_f16(float* c, const uint32_t* a, const uint32_t* b) {
    asm volatile(
        "mma.sync.aligned.m16n8k16.row.col.f32.f16.f16.f32 "
        "{%0,%1,%2,%3}, {%4,%5,%6,%7}, {%8,%9}, {%0,%1,%2,%3};"
        : "+f"(c[0]), "+f"(c[1]), "+f"(c[2]), "+f"(c[3])
        : "r"(a[0]), "r"(a[1]), "r"(a[2]), "r"(a[3]), "r"(b[0]), "r"(b[1]));
}
#define LDSM4(d, a) \
    asm volatile("ldmatrix.sync.aligned.m8n8.x4.shared.b16 {%0,%1,%2,%3}, [%4];" \
        : "=r"((d)[0]), "=r"((d)[1]), "=r"((d)[2]), "=r"((d)[3]) : "r"(a))

// ---------------- merged fp32 -> fp16 conversion (all 7 tensors) ---------------
struct ConvSeg { const float4* src; __half2* dst; int n4; };

__global__ void tohalf_all_k(ConvSeg s0, ConvSeg s1, ConvSeg s2, ConvSeg s3,
                             ConvSeg s4, ConvSeg s5, ConvSeg s6, int total4) {
    ConvSeg segs[7] = {s0, s1, s2, s3, s4, s5, s6};
    for (int i = blockIdx.x * blockDim.x + threadIdx.x; i < total4;
         i += gridDim.x * blockDim.x) {
        int r = i;
        #pragma unroll
        for (int k = 0; k < 7; k++) {
            if (r < segs[k].n4) {
                float4 v = segs[k].src[r];
                segs[k].dst[2 * r + 0] = __floats2half2_rn(v.x, v.y);
                segs[k].dst[2 * r + 1] = __floats2half2_rn(v.z, v.w);
                break;
            }
            r -= segs[k].n4;
        }
    }
}

// ---------------- Z reduce: sum split-K partials, mask, scale, -> half ---------
template<int SPLIT>
__global__ void zreduce_k(const float* __restrict__ Zp, const int* __restrict__ eidx,
                          __half* __restrict__ Z) {
    int idx = blockIdx.x * blockDim.x + threadIdx.x;   // t*ER + j
    int t = idx >> 7, j = idx & 127;
    float v = 0.f;
    if ((j >> 4) == eidx[t]) {
        #pragma unroll
        for (int s = 0; s < SPLIT; s++) v += Zp[(size_t)s * TT * ER + idx];
        v *= SCAL;
    }
    Z[idx] = __float2half_rn(v);
}

// ---------------- fc2 output reduce: sum SPLITF partials + bias ----------------
__global__ void oreduce_k(const float* __restrict__ P, const float* __restrict__ bias,
                          float* __restrict__ out) {
    size_t i4 = (size_t)blockIdx.x * blockDim.x + threadIdx.x;   // float4 index
    const float4* P4 = (const float4*)P;
    const size_t st4 = (size_t)TT * DD / 4;
    float4 a = P4[i4], b = P4[i4 + st4], c = P4[i4 + 2 * st4], d = P4[i4 + 3 * st4];
    int col = ((int)i4 * 4) & (DD - 1);
    float4 bb = *reinterpret_cast<const float4*>(bias + col);
    float4 o;
    o.x = a.x + b.x + c.x + d.x + bb.x;
    o.y = a.y + b.y + c.y + d.y + bb.y;
    o.z = a.z + b.z + c.z + d.z + bb.z;
    o.w = a.w + b.w + c.w + d.w + bb.w;
    reinterpret_cast<float4*>(out)[i4] = o;
}

// ---------------- fp16 GEMM: C[T,N] = [A0|AL] @ [W|BL]^T -----------------------
// 3-stage cp.async ring, one __syncthreads per ktile, BK=64, ldmatrix fragments,
// 4 warps of 64x64 (128 threads). Loader split into fast main path + LoRA tail.
// PART: split-K partial to slab at blockIdx.z * TT * Nsz (fp32, no bias).
template<int K0, bool TAIL, bool GELU, bool PART>
__global__ void __launch_bounds__(NTHR, 2)
moe_gemm_h(const __half* __restrict__ A0, const __half* __restrict__ AL,
           const __half* __restrict__ W,  const __half* __restrict__ BL,
           const float* __restrict__ bias, void* __restrict__ Cout,
           int Nsz, int nkt, int kch) {
    extern __shared__ __align__(128) char smem[];
    int NK = nkt;
    if (PART && TAIL && blockIdx.z == gridDim.z - 1) NK += ER / BK;
    const int kbase = PART ? blockIdx.z * kch : 0;
    const int m0 = blockIdx.y * BM, n0 = blockIdx.x * BN;
    const int tid  = threadIdx.x;
    const int warp = tid >> 5, wm = warp >> 1, wn = warp & 1;   // 2x2 warps, 64x64
    const int lane = tid & 31, grp = lane >> 2, tig = lane & 3;
    const int lr = tid >> 3, lc = tid & 7;                       // loader: 16 rows x 8 chunks

    float acc[4][8][4];
    #pragma unroll
    for (int i = 0; i < 4; i++)
        #pragma unroll
        for (int j = 0; j < 8; j++)
            #pragma unroll
            for (int c = 0; c < 4; c++) acc[i][j][c] = 0.f;

    const uint32_t sA = (uint32_t)__cvta_generic_to_shared(smem);
    const uint32_t sB = sA + NS * TILEB;

    // ldmatrix per-lane base addresses (stage 0)
    const int l7 = lane & 7, lb = (lane >> 3) & 1, lh = lane >> 4;
    const uint32_t lmA = sA + (uint32_t)((wm * 64 + l7 + lb * 8) * ROWB + lh * 16);
    const uint32_t lmB = sB + (uint32_t)((wn * 64 + l7 + lh * 8) * ROWB + lb * 16);

    // precomputed loader bases (main path)
    const __half* gA0 = A0 + (size_t)(m0 + lr) * K0 + kbase + lc * 8;
    const __half* gB0 = W  + (size_t)(n0 + lr) * K0 + kbase + lc * 8;
    const uint32_t dA0 = sA + (uint32_t)(lr * ROWB + lc * 16);
    const uint32_t dB0 = sB + (uint32_t)(lr * ROWB + lc * 16);

    auto load_tiles = [&](int kt, int buf) {
        if (!TAIL || kbase + kt * BK < K0) {
            const __half* gA = gA0 + kt * BK;
            const __half* gB = gB0 + kt * BK;
            uint32_t dA = dA0 + buf * TILEB;
            uint32_t dB = dB0 + buf * TILEB;
            #pragma unroll
            for (int p = 0; p < 8; p++) {
                cp16(dA + p * (16 * ROWB), gA + (size_t)p * 16 * K0);
                cp16(dB + p * (16 * ROWB), gB + (size_t)p * 16 * K0);
            }
        } else {
            int j = kbase + kt * BK + lc * 8 - K0;   // 0..127: e=j>>4, r=j&15
            #pragma unroll
            for (int p = 0; p < 8; p++) {
                int row = lr + p * 16;
                cp16(dA0 + buf * TILEB + p * (16 * ROWB),
                     AL + (size_t)(m0 + row) * ER + j);
                cp16(dB0 + buf * TILEB + p * (16 * ROWB),
                     BL + ((size_t)(j >> 4) * Nsz + (n0 + row)) * RRK + (j & 15));
            }
        }
    };

    load_tiles(0, 0);
    asm volatile("cp.async.commit_group;");
    load_tiles(1, 1);
    asm volatile("cp.async.commit_group;");

    int s = 0;
    for (int kt = 0; kt < NK; ++kt) {
        asm volatile("cp.async.wait_group 1;");
        __syncthreads();

        if (kt + 2 < NK) load_tiles(kt + 2, (kt + 2) % NS);
        asm volatile("cp.async.commit_group;");

        const uint32_t stA = lmA + s * TILEB;
        const uint32_t stB = lmB + s * TILEB;
        #pragma unroll
        for (int s2 = 0; s2 < 4; s2++) {               // four k16 slices
            uint32_t af[4][4], bf[4][4];
            #pragma unroll
            for (int i = 0; i < 4; i++)
                LDSM4(af[i], stA + i * (16 * ROWB) + s2 * 32);
            #pragma unroll
            for (int p = 0; p < 4; p++)
                LDSM4(bf[p], stB + p * (16 * ROWB) + s2 * 32);
            #pragma unroll
            for (int i = 0; i < 4; i++)
                #pragma unroll
                for (int p = 0; p < 4; p++) {
                    mma_f16(acc[i][2 * p + 0], af[i], &bf[p][0]);
                    mma_f16(acc[i][2 * p + 1], af[i], &bf[p][2]);
                }
        }
        s = (s == NS - 1) ? 0 : s + 1;
    }

    // epilogue
    #pragma unroll
    for (int i = 0; i < 4; i++) {
        int t0 = m0 + wm * 64 + i * 16 + grp;
        #pragma unroll
        for (int j = 0; j < 8; j++) {
            int n = n0 + wn * 64 + j * 8 + 2 * tig;
            if (PART) {
                float* C = (float*)Cout + (size_t)blockIdx.z * TT * Nsz;
                float2 v0 = {acc[i][j][0], acc[i][j][1]};
                float2 v1 = {acc[i][j][2], acc[i][j][3]};
                *reinterpret_cast<float2*>(&C[(size_t)t0 * Nsz + n]) = v0;
                *reinterpret_cast<float2*>(&C[(size_t)(t0 + 8) * Nsz + n]) = v1;
            } else if (GELU) {
                __half2* C = (__half2*)Cout;
                float bv0 = bias[n], bv1 = bias[n + 1];
                C[((size_t)t0 * Nsz + n) >> 1] = __floats2half2_rn(
                    gelu_new_f(acc[i][j][0] + bv0), gelu_new_f(acc[i][j][1] + bv1));
                C[((size_t)(t0 + 8) * Nsz + n) >> 1] = __floats2half2_rn(
                    gelu_new_f(acc[i][j][2] + bv0), gelu_new_f(acc[i][j][3] + bv1));
            } else {
                float* C = (float*)Cout;
                float bv0 = bias[n], bv1 = bias[n + 1];
                float2 v0 = {acc[i][j][0] + bv0, acc[i][j][1] + bv1};
                float2 v1 = {acc[i][j][2] + bv0, acc[i][j][3] + bv1};
                *reinterpret_cast<float2*>(&C[(size_t)t0 * Nsz + n]) = v0;
                *reinterpret_cast<float2*>(&C[(size_t)(t0 + 8) * Nsz + n]) = v1;
            }
        }
    }
}

// ---------------- launch --------------------------------------------------------
extern "C" void kernel_launch(void* const* d_in, const int* in_sizes, int n_in,
                              void* d_out, int out_size) {
    const float* x  = (const float*)d_in[0];
    const int*   ei = (const int*)  d_in[1];
    const float* W1 = (const float*)d_in[2];
    const float* b1 = (const float*)d_in[3];
    const float* A1 = (const float*)d_in[4];
    const float* B1 = (const float*)d_in[5];
    const float* W2 = (const float*)d_in[6];
    const float* b2 = (const float*)d_in[7];
    const float* A2 = (const float*)d_in[8];
    const float* B2 = (const float*)d_in[9];
    float* out = (float*)d_out;

    __half *pW1, *pW2, *pB1, *pB2, *pA1, *pA2, *pX, *pY, *pZ1, *pZ2;
    float* pP;
    cudaGetSymbolAddress((void**)&pW1, g_W1h);
    cudaGetSymbolAddress((void**)&pW2, g_W2h);
    cudaGetSymbolAddress((void**)&pB1, g_B1h);
    cudaGetSymbolAddress((void**)&pB2, g_B2h);
    cudaGetSymbolAddress((void**)&pA1, g_A1h);
    cudaGetSymbolAddress((void**)&pA2, g_A2h);
    cudaGetSymbolAddress((void**)&pX,  g_Xh);
    cudaGetSymbolAddress((void**)&pY,  g_Yh);
    cudaGetSymbolAddress((void**)&pZ1, g_Z1h);
    cudaGetSymbolAddress((void**)&pZ2, g_Z2h);
    cudaGetSymbolAddress((void**)&pP,  g_part);

    cudaFuncSetAttribute(moe_gemm_h<DD, true,  true,  false>,
                         cudaFuncAttributeMaxDynamicSharedMemorySize, SMEMSZ);
    cudaFuncSetAttribute(moe_gemm_h<HH, true,  false, true>,
                         cudaFuncAttributeMaxDynamicSharedMemorySize, SMEMSZ);
    cudaFuncSetAttribute(moe_gemm_h<DD, false, false, true>,
                         cudaFuncAttributeMaxDynamicSharedMemorySize, SMEMSZ);
    cudaFuncSetAttribute(moe_gemm_h<HH, false, false, true>,
                         cudaFuncAttributeMaxDynamicSharedMemorySize, SMEMSZ);

    // one merged conversion for all 7 tensors
    ConvSeg s0 = {(const float4*)W1, (__half2*)pW1, HH * DD / 4};
    ConvSeg s1 = {(const float4*)W2, (__half2*)pW2, DD * HH / 4};
    ConvSeg s2 = {(const float4*)x,  (__half2*)pX,  TT * DD / 4};
    ConvSeg s3 = {(const float4*)B1, (__half2*)pB1, NE * HH * RRK / 4};
    ConvSeg s4 = {(const float4*)B2, (__half2*)pB2, NE * DD * RRK / 4};
    ConvSeg s5 = {(const float4*)A1, (__half2*)pA1, ER * DD / 4};
    ConvSeg s6 = {(const float4*)A2, (__half2*)pA2, ER * HH / 4};
    int total4 = s0.n4 + s1.n4 + s2.n4 + s3.n4 + s4.n4 + s5.n4 + s6.n4;
    tohalf_all_k<<<2048, 256>>>(s0, s1, s2, s3, s4, s5, s6, total4);

    // Z1 partials: split-K over K=2048 (4 chunks of 512)
    moe_gemm_h<DD, false, false, true><<<dim3(1, TT / BM, SPLIT1), NTHR, SMEMSZ>>>(
        pX, nullptr, pA1, nullptr, nullptr, pP, ER, (DD / SPLIT1) / BK, DD / SPLIT1);
    zreduce_k<SPLIT1><<<TT * ER / 256, 256>>>(pP, ei, pZ1);

    // fc1: Y = half(gelu(X@W1^T + b1 + Z1@B1^T))
    moe_gemm_h<DD, true, true, false><<<dim3(HH / BN, TT / BM), NTHR, SMEMSZ>>>(
        pX, pZ1, pW1, pB1, b1, pY, HH, (DD + ER) / BK, 0);

    // Z2 partials: split-K over K=8192 (8 chunks of 1024)
    moe_gemm_h<HH, false, false, true><<<dim3(1, TT / BM, SPLIT2), NTHR, SMEMSZ>>>(
        pY, nullptr, pA2, nullptr, nullptr, pP, ER, (HH / SPLIT2) / BK, HH / SPLIT2);
    zreduce_k<SPLIT2><<<TT * ER / 256, 256>>>(pP, ei, pZ2);

    // fc2 partials: split-K=4 over K=8192 (+ LoRA tail on z=3)
    moe_gemm_h<HH, true, false, true><<<dim3(DD / BN, TT / BM, SPLITF), NTHR, SMEMSZ>>>(
        pY, pZ2, pW2, pB2, nullptr, pP, DD, (HH / SPLITF) / BK, HH / SPLITF);

    // out = sum partials + b2
    oreduce_k<<<TT * DD / 4 / 256, 256>>>(pP, b2, out);
}

// round 16
// speedup vs baseline: 1.0535x; 1.0535x over previous
#include <cuda_runtime.h>
#include <cuda_fp16.h>
#include <cstdint>

#define TT 4096
#define DD 2048
#define HH 8192
#define NE 8
#define RRK 16
#define ER 128
#define SCAL 2.0f

#define BM 128
#define BN 128
#define BK 64                  // 64 halfs of K per tile
#define NS 3
#define RS 36                  // smem row stride in words (144 B) — LDS & ldmatrix conflict-free
#define ROWB 144
#define TILEB (BM * RS * 4)    // 18432 B per operand tile
#define SMEMSZ (NS * 2 * TILEB) // 110592 B -> 2 CTAs/SM
#define NTHR 128               // 4 warps (2x2 of 64x64)

#define SPLIT1 4
#define SPLIT2 8
#define SPLITF 4               // fc2 split-K factor

// ---------------- scratch (device globals) ------------------------------------
__device__ __half g_W1h[(size_t)HH * DD];
__device__ __half g_W2h[(size_t)DD * HH];
__device__ __half g_B1h[(size_t)NE * HH * RRK];
__device__ __half g_B2h[(size_t)NE * DD * RRK];
__device__ __half g_A1h[(size_t)ER * DD];
__device__ __half g_A2h[(size_t)ER * HH];
__device__ __half g_Xh [(size_t)TT * DD];
__device__ __half g_Yh [(size_t)TT * HH];
__device__ __half g_Z1h[TT * ER];
__device__ __half g_Z2h[TT * ER];
__device__ float  g_part[(size_t)SPLITF * TT * DD];  // split-K partial slab (fc2 & Z)

// ---------------- helpers ------------------------------------------------------
__device__ __forceinline__ void cp16(uint32_t s, const void* g) {
    asm volatile("cp.async.cg.shared.global [%0], [%1], 16;" :: "r"(s), "l"(g));
}
__device__ __forceinline__ float gelu_new_f(float x) {
    float u = 0.7978845608028654f * x * (1.0f + 0.044715f * x * x);
    float t;
    asm("tanh.approx.f32 %0, %1;" : "=f"(t) : "f"(u));   // HW MUFU.TANH
    return 0.5f * x * (1.0f + t);
}
__device__ __forceinline__ void mma_f16(float* c, const uint32_t* a, const uint32_t* b) {
    asm volatile(
        "mma.sync.aligned.m16n8k16.row.col.f32.f16.f16.f32 "
        "{%0,%1,%2,%3}, {%4,%5,%6,%7}, {%8,%9}, {%0,%1,%2,%3};"
        : "+f"(c[0]), "+f"(c[1]), "+f"(c[2]), "+f"(c[3])
        : "r"(a[0]), "r"(a[1]), "r"(a[2]), "r"(a[3]), "r"(b[0]), "r"(b[1]));
}
#define LDSM4(d, a) \
    asm volatile("ldmatrix.sync.aligned.m8n8.x4.shared.b16 {%0,%1,%2,%3}, [%4];" \
        : "=r"((d)[0]), "=r"((d)[1]), "=r"((d)[2]), "=r"((d)[3]) : "r"(a))

// ---------------- merged fp32 -> fp16 conversion (all 7 tensors) ---------------
struct ConvSeg { const float4* src; __half2* dst; int n4; };

__global__ void tohalf_all_k(ConvSeg s0, ConvSeg s1, ConvSeg s2, ConvSeg s3,
                             ConvSeg s4, ConvSeg s5, ConvSeg s6, int total4) {
    ConvSeg segs[7] = {s0, s1, s2, s3, s4, s5, s6};
    for (int i = blockIdx.x * blockDim.x + threadIdx.x; i < total4;
         i += gridDim.x * blockDim.x) {
        int r = i;
        #pragma unroll
        for (int k = 0; k < 7; k++) {
            if (r < segs[k].n4) {
                float4 v = segs[k].src[r];
                segs[k].dst[2 * r + 0] = __floats2half2_rn(v.x, v.y);
                segs[k].dst[2 * r + 1] = __floats2half2_rn(v.z, v.w);
                break;
            }
            r -= segs[k].n4;
        }
    }
}

// ---------------- Z reduce: sum split-K partials, mask, scale, -> half ---------
template<int SPLIT>
__global__ void zreduce_k(const float* __restrict__ Zp, const int* __restrict__ eidx,
                          __half* __restrict__ Z) {
    int idx = blockIdx.x * blockDim.x + threadIdx.x;   // t*ER + j
    int t = idx >> 7, j = idx & 127;
    float v = 0.f;
    if ((j >> 4) == eidx[t]) {
        #pragma unroll
        for (int s = 0; s < SPLIT; s++) v += Zp[(size_t)s * TT * ER + idx];
        v *= SCAL;
    }
    Z[idx] = __float2half_rn(v);
}

// ---------------- fc2 output reduce: sum SPLITF partials + bias ----------------
__global__ void oreduce_k(const float* __restrict__ P, const float* __restrict__ bias,
                          float* __restrict__ out) {
    size_t i4 = (size_t)blockIdx.x * blockDim.x + threadIdx.x;   // float4 index
    const float4* P4 = (const float4*)P;
    const size_t st4 = (size_t)TT * DD / 4;
    float4 a = P4[i4], b = P4[i4 + st4], c = P4[i4 + 2 * st4], d = P4[i4 + 3 * st4];
    int col = ((int)i4 * 4) & (DD - 1);
    float4 bb = *reinterpret_cast<const float4*>(bias + col);
    float4 o;
    o.x = a.x + b.x + c.x + d.x + bb.x;
    o.y = a.y + b.y + c.y + d.y + bb.y;
    o.z = a.z + b.z + c.z + d.z + bb.z;
    o.w = a.w + b.w + c.w + d.w + bb.w;
    reinterpret_cast<float4*>(out)[i4] = o;
}

// ---------------- fp16 GEMM: C[T,N] = [A0|AL] @ [W|BL]^T -----------------------
// 3-stage cp.async ring, one __syncthreads per ktile, BK=64, ldmatrix fragments,
// 4 warps of 64x64 (128 threads). Loader split into fast main path + LoRA tail.
// PART: split-K partial to slab at blockIdx.z * TT * Nsz (fp32, no bias).
template<int K0, bool TAIL, bool GELU, bool PART>
__global__ void __launch_bounds__(NTHR, 2)
moe_gemm_h(const __half* __restrict__ A0, const __half* __restrict__ AL,
           const __half* __restrict__ W,  const __half* __restrict__ BL,
           const float* __restrict__ bias, void* __restrict__ Cout,
           int Nsz, int nkt, int kch) {
    extern __shared__ __align__(128) char smem[];
    int NK = nkt;
    if (PART && TAIL && blockIdx.z == gridDim.z - 1) NK += ER / BK;
    const int kbase = PART ? blockIdx.z * kch : 0;
    const int m0 = blockIdx.y * BM, n0 = blockIdx.x * BN;
    const int tid  = threadIdx.x;
    const int warp = tid >> 5, wm = warp >> 1, wn = warp & 1;   // 2x2 warps, 64x64
    const int lane = tid & 31, grp = lane >> 2, tig = lane & 3;
    const int lr = tid >> 3, lc = tid & 7;                       // loader: 16 rows x 8 chunks

    float acc[4][8][4];
    #pragma unroll
    for (int i = 0; i < 4; i++)
        #pragma unroll
        for (int j = 0; j < 8; j++)
            #pragma unroll
            for (int c = 0; c < 4; c++) acc[i][j][c] = 0.f;

    const uint32_t sA = (uint32_t)__cvta_generic_to_shared(smem);
    const uint32_t sB = sA + NS * TILEB;

    // ldmatrix per-lane base addresses (stage 0)
    const int l7 = lane & 7, lb = (lane >> 3) & 1, lh = lane >> 4;
    const uint32_t lmA = sA + (uint32_t)((wm * 64 + l7 + lb * 8) * ROWB + lh * 16);
    const uint32_t lmB = sB + (uint32_t)((wn * 64 + l7 + lh * 8) * ROWB + lb * 16);

    // precomputed loader bases (main path)
    const __half* gA0 = A0 + (size_t)(m0 + lr) * K0 + kbase + lc * 8;
    const __half* gB0 = W  + (size_t)(n0 + lr) * K0 + kbase + lc * 8;
    const uint32_t dA0 = sA + (uint32_t)(lr * ROWB + lc * 16);
    const uint32_t dB0 = sB + (uint32_t)(lr * ROWB + lc * 16);

    auto load_tiles = [&](int kt, int buf) {
        if (!TAIL || kbase + kt * BK < K0) {
            const __half* gA = gA0 + kt * BK;
            const __half* gB = gB0 + kt * BK;
            uint32_t dA = dA0 + buf * TILEB;
            uint32_t dB = dB0 + buf * TILEB;
            #pragma unroll
            for (int p = 0; p < 8; p++) {
                cp16(dA + p * (16 * ROWB), gA + (size_t)p * 16 * K0);
                cp16(dB + p * (16 * ROWB), gB + (size_t)p * 16 * K0);
            }
        } else {
            int j = kbase + kt * BK + lc * 8 - K0;   // 0..127: e=j>>4, r=j&15
            #pragma unroll
            for (int p = 0; p < 8; p++) {
                int row = lr + p * 16;
                cp16(dA0 + buf * TILEB + p * (16 * ROWB),
                     AL + (size_t)(m0 + row) * ER + j);
                cp16(dB0 + buf * TILEB + p * (16 * ROWB),
                     BL + ((size_t)(j >> 4) * Nsz + (n0 + row)) * RRK + (j & 15));
            }
        }
    };

    load_tiles(0, 0);
    asm volatile("cp.async.commit_group;");
    load_tiles(1, 1);
    asm volatile("cp.async.commit_group;");

    int s = 0;
    for (int kt = 0; kt < NK; ++kt) {
        asm volatile("cp.async.wait_group 1;");
        __syncthreads();

        if (kt + 2 < NK) load_tiles(kt + 2, (kt + 2) % NS);
        asm volatile("cp.async.commit_group;");

        const uint32_t stA = lmA + s * TILEB;
        const uint32_t stB = lmB + s * TILEB;
        #pragma unroll
        for (int s2 = 0; s2 < 4; s2++) {               // four k16 slices
            uint32_t af[4][4], bf[4][4];
            #pragma unroll
            for (int i = 0; i < 4; i++)
                LDSM4(af[i], stA + i * (16 * ROWB) + s2 * 32);
            #pragma unroll
            for (int p = 0; p < 4; p++)
                LDSM4(bf[p], stB + p * (16 * ROWB) + s2 * 32);
            #pragma unroll
            for (int i = 0; i < 4; i++)
                #pragma unroll
                for (int p = 0; p < 4; p++) {
                    mma_f16(acc[i][2 * p + 0], af[i], &bf[p][0]);
                    mma_f16(acc[i][2 * p + 1], af[i], &bf[p][2]);
                }
        }
        s = (s == NS - 1) ? 0 : s + 1;
    }

    // epilogue
    #pragma unroll
    for (int i = 0; i < 4; i++) {
        int t0 = m0 + wm * 64 + i * 16 + grp;
        #pragma unroll
        for (int j = 0; j < 8; j++) {
            int n = n0 + wn * 64 + j * 8 + 2 * tig;
            if (PART) {
                float* C = (float*)Cout + (size_t)blockIdx.z * TT * Nsz;
                float2 v0 = {acc[i][j][0], acc[i][j][1]};
                float2 v1 = {acc[i][j][2], acc[i][j][3]};
                *reinterpret_cast<float2*>(&C[(size_t)t0 * Nsz + n]) = v0;
                *reinterpret_cast<float2*>(&C[(size_t)(t0 + 8) * Nsz + n]) = v1;
            } else if (GELU) {
                __half2* C = (__half2*)Cout;
                float bv0 = bias[n], bv1 = bias[n + 1];
                C[((size_t)t0 * Nsz + n) >> 1] = __floats2half2_rn(
                    gelu_new_f(acc[i][j][0] + bv0), gelu_new_f(acc[i][j][1] + bv1));
                C[((size_t)(t0 + 8) * Nsz + n) >> 1] = __floats2half2_rn(
                    gelu_new_f(acc[i][j][2] + bv0), gelu_new_f(acc[i][j][3] + bv1));
            } else {
                float* C = (float*)Cout;
                float bv0 = bias[n], bv1 = bias[n + 1];
                float2 v0 = {acc[i][j][0] + bv0, acc[i][j][1] + bv1};
                float2 v1 = {acc[i][j][2] + bv0, acc[i][j][3] + bv1};
                *reinterpret_cast<float2*>(&C[(size_t)t0 * Nsz + n]) = v0;
                *reinterpret_cast<float2*>(&C[(size_t)(t0 + 8) * Nsz + n]) = v1;
            }
        }
    }
}

// ---------------- launch --------------------------------------------------------
extern "C" void kernel_launch(void* const* d_in, const int* in_sizes, int n_in,
                              void* d_out, int out_size) {
    const float* x  = (const float*)d_in[0];
    const int*   ei = (const int*)  d_in[1];
    const float* W1 = (const float*)d_in[2];
    const float* b1 = (const float*)d_in[3];
    const float* A1 = (const float*)d_in[4];
    const float* B1 = (const float*)d_in[5];
    const float* W2 = (const float*)d_in[6];
    const float* b2 = (const float*)d_in[7];
    const float* A2 = (const float*)d_in[8];
    const float* B2 = (const float*)d_in[9];
    float* out = (float*)d_out;

    __half *pW1, *pW2, *pB1, *pB2, *pA1, *pA2, *pX, *pY, *pZ1, *pZ2;
    float* pP;
    cudaGetSymbolAddress((void**)&pW1, g_W1h);
    cudaGetSymbolAddress((void**)&pW2, g_W2h);
    cudaGetSymbolAddress((void**)&pB1, g_B1h);
    cudaGetSymbolAddress((void**)&pB2, g_B2h);
    cudaGetSymbolAddress((void**)&pA1, g_A1h);
    cudaGetSymbolAddress((void**)&pA2, g_A2h);
    cudaGetSymbolAddress((void**)&pX,  g_Xh);
    cudaGetSymbolAddress((void**)&pY,  g_Yh);
    cudaGetSymbolAddress((void**)&pZ1, g_Z1h);
    cudaGetSymbolAddress((void**)&pZ2, g_Z2h);
    cudaGetSymbolAddress((void**)&pP,  g_part);

    cudaFuncSetAttribute(moe_gemm_h<DD, true,  true,  false>,
                         cudaFuncAttributeMaxDynamicSharedMemorySize, SMEMSZ);
    cudaFuncSetAttribute(moe_gemm_h<HH, true,  false, true>,
                         cudaFuncAttributeMaxDynamicSharedMemorySize, SMEMSZ);
    cudaFuncSetAttribute(moe_gemm_h<DD, false, false, true>,
                         cudaFuncAttributeMaxDynamicSharedMemorySize, SMEMSZ);
    cudaFuncSetAttribute(moe_gemm_h<HH, false, false, true>,
                         cudaFuncAttributeMaxDynamicSharedMemorySize, SMEMSZ);

    // one merged conversion for all 7 tensors
    ConvSeg s0 = {(const float4*)W1, (__half2*)pW1, HH * DD / 4};
    ConvSeg s1 = {(const float4*)W2, (__half2*)pW2, DD * HH / 4};
    ConvSeg s2 = {(const float4*)x,  (__half2*)pX,  TT * DD / 4};
    ConvSeg s3 = {(const float4*)B1, (__half2*)pB1, NE * HH * RRK / 4};
    ConvSeg s4 = {(const float4*)B2, (__half2*)pB2, NE * DD * RRK / 4};
    ConvSeg s5 = {(const float4*)A1, (__half2*)pA1, ER * DD / 4};
    ConvSeg s6 = {(const float4*)A2, (__half2*)pA2, ER * HH / 4};
    int total4 = s0.n4 + s1.n4 + s2.n4 + s3.n4 + s4.n4 + s5.n4 + s6.n4;
    tohalf_all_k<<<2048, 256>>>(s0, s1, s2, s3, s4, s5, s6, total4);

    // Z1 partials: split-K over K=2048 (4 chunks of 512)
    moe_gemm_h<DD, false, false, true><<<dim3(1, TT / BM, SPLIT1), NTHR, SMEMSZ>>>(
        pX, nullptr, pA1, nullptr, nullptr, pP, ER, (DD / SPLIT1) / BK, DD / SPLIT1);
    zreduce_k<SPLIT1><<<TT * ER / 256, 256>>>(pP, ei, pZ1);

    // fc1: Y = half(gelu(X@W1^T + b1 + Z1@B1^T))
    moe_gemm_h<DD, true, true, false><<<dim3(HH / BN, TT / BM), NTHR, SMEMSZ>>>(
        pX, pZ1, pW1, pB1, b1, pY, HH, (DD + ER) / BK, 0);

    // Z2 partials: split-K over K=8192 (8 chunks of 1024)
    moe_gemm_h<HH, false, false, true><<<dim3(1, TT / BM, SPLIT2), NTHR, SMEMSZ>>>(
        pY, nullptr, pA2, nullptr, nullptr, pP, ER, (HH / SPLIT2) / BK, HH / SPLIT2);
    zreduce_k<SPLIT2><<<TT * ER / 256, 256>>>(pP, ei, pZ2);

    // fc2 partials: split-K=4 over K=8192 (+ LoRA tail on z=3)
    moe_gemm_h<HH, true, false, true><<<dim3(DD / BN, TT / BM, SPLITF), NTHR, SMEMSZ>>>(
        pY, pZ2, pW2, pB2, nullptr, pP, DD, (HH / SPLITF) / BK, HH / SPLITF);

    // out = sum partials + b2
    oreduce_k<<<TT * DD / 4 / 256, 256>>>(pP, b2, out);
}

// round 17
// speedup vs baseline: 1.0556x; 1.0019x over previous
#include <cuda_runtime.h>
#include <cuda_fp16.h>
#include <cstdint>

#define TT 4096
#define DD 2048
#define HH 8192
#define NE 8
#define RRK 16
#define ER 128
#define SCAL 2.0f

#define BM 128
#define BN 128
#define BK 64                  // 64 halfs of K per tile
#define NS 3
#define RS 36                  // smem row stride in words (144 B) — LDS & ldmatrix conflict-free
#define ROWB 144
#define TILEB (BM * RS * 4)    // 18432 B per operand tile
#define SMEMSZ (NS * 2 * TILEB) // 110592 B -> 2 CTAs/SM
#define NTHR 128               // 4 warps (2x2 of 64x64)

#define SPLIT1 4
#define SPLIT2 8
#define SPLITF 4               // fc2 split-K factor

// ---------------- scratch (device globals) ------------------------------------
__device__ __half g_W1h[(size_t)HH * DD];
__device__ __half g_W2h[(size_t)DD * HH];
__device__ __half g_B1h[(size_t)NE * HH * RRK];
__device__ __half g_B2h[(size_t)NE * DD * RRK];
__device__ __half g_A1h[(size_t)ER * DD];
__device__ __half g_A2h[(size_t)ER * HH];
__device__ __half g_Xh [(size_t)TT * DD];
__device__ __half g_Yh [(size_t)TT * HH];
__device__ __half g_Z1h[TT * ER];
__device__ __half g_Z2h[TT * ER];
__device__ float  g_part[(size_t)SPLITF * TT * DD];  // split-K partial slab (fc2 & Z)

// ---------------- helpers ------------------------------------------------------
__device__ __forceinline__ void cp16(uint32_t s, const void* g) {
    asm volatile("cp.async.cg.shared.global [%0], [%1], 16;" :: "r"(s), "l"(g));
}
__device__ __forceinline__ float gelu_new_f(float x) {
    float u = 0.7978845608028654f * x * (1.0f + 0.044715f * x * x);
    float t;
    asm("tanh.approx.f32 %0, %1;" : "=f"(t) : "f"(u));   // HW MUFU.TANH
    return 0.5f * x * (1.0f + t);
}
__device__ __forceinline__ void mma_f16(float* c, const uint32_t* a, const uint32_t* b) {
    asm volatile(
        "mma.sync.aligned.m16n8k16.row.col.f32.f16.f16.f32 "
        "{%0,%1,%2,%3}, {%4,%5,%6,%7}, {%8,%9}, {%0,%1,%2,%3};"
        : "+f"(c[0]), "+f"(c[1]), "+f"(c[2]), "+f"(c[3])
        : "r"(a[0]), "r"(a[1]), "r"(a[2]), "r"(a[3]), "r"(b[0]), "r"(b[1]));
}
#define LDSM4(d, a) \
    asm volatile("ldmatrix.sync.aligned.m8n8.x4.shared.b16 {%0,%1,%2,%3}, [%4];" \
        : "=r"((d)[0]), "=r"((d)[1]), "=r"((d)[2]), "=r"((d)[3]) : "r"(a))

// ---------------- merged fp32 -> fp16 conversion (all 7 tensors) ---------------
struct ConvSeg { const float4* src; __half2* dst; int n4; };

__global__ void tohalf_all_k(ConvSeg s0, ConvSeg s1, ConvSeg s2, ConvSeg s3,
                             ConvSeg s4, ConvSeg s5, ConvSeg s6, int total4) {
    ConvSeg segs[7] = {s0, s1, s2, s3, s4, s5, s6};
    for (int i = blockIdx.x * blockDim.x + threadIdx.x; i < total4;
         i += gridDim.x * blockDim.x) {
        int r = i;
        #pragma unroll
        for (int k = 0; k < 7; k++) {
            if (r < segs[k].n4) {
                float4 v = segs[k].src[r];
                segs[k].dst[2 * r + 0] = __floats2half2_rn(v.x, v.y);
                segs[k].dst[2 * r + 1] = __floats2half2_rn(v.z, v.w);
                break;
            }
            r -= segs[k].n4;
        }
    }
}

// ---------------- Z reduce: sum split-K partials, mask, scale, -> half ---------
template<int SPLIT>
__global__ void zreduce_k(const float* __restrict__ Zp, const int* __restrict__ eidx,
                          __half* __restrict__ Z) {
    int idx = blockIdx.x * blockDim.x + threadIdx.x;   // t*ER + j
    int t = idx >> 7, j = idx & 127;
    float v = 0.f;
    if ((j >> 4) == eidx[t]) {
        #pragma unroll
        for (int s = 0; s < SPLIT; s++) v += Zp[(size_t)s * TT * ER + idx];
        v *= SCAL;
    }
    Z[idx] = __float2half_rn(v);
}

// ---------------- fc2 output reduce: sum SPLITF partials + bias ----------------
__global__ void oreduce_k(const float* __restrict__ P, const float* __restrict__ bias,
                          float* __restrict__ out) {
    size_t i4 = (size_t)blockIdx.x * blockDim.x + threadIdx.x;   // float4 index
    const float4* P4 = (const float4*)P;
    const size_t st4 = (size_t)TT * DD / 4;
    float4 a = P4[i4], b = P4[i4 + st4], c = P4[i4 + 2 * st4], d = P4[i4 + 3 * st4];
    int col = ((int)i4 * 4) & (DD - 1);
    float4 bb = *reinterpret_cast<const float4*>(bias + col);
    float4 o;
    o.x = a.x + b.x + c.x + d.x + bb.x;
    o.y = a.y + b.y + c.y + d.y + bb.y;
    o.z = a.z + b.z + c.z + d.z + bb.z;
    o.w = a.w + b.w + c.w + d.w + bb.w;
    reinterpret_cast<float4*>(out)[i4] = o;
}

// ---------------- fp16 GEMM: C[T,N] = [A0|AL] @ [W|BL]^T -----------------------
// 3-stage cp.async ring, one __syncthreads per ktile, BK=64, ldmatrix fragments,
// 4 warps of 64x64 (128 threads), explicit ping-pong fragment double-buffering.
// PART: split-K partial to slab at blockIdx.z * TT * Nsz (fp32, no bias).
template<int K0, bool TAIL, bool GELU, bool PART>
__global__ void __launch_bounds__(NTHR, 2)
moe_gemm_h(const __half* __restrict__ A0, const __half* __restrict__ AL,
           const __half* __restrict__ W,  const __half* __restrict__ BL,
           const float* __restrict__ bias, void* __restrict__ Cout,
           int Nsz, int nkt, int kch) {
    extern __shared__ __align__(128) char smem[];
    int NK = nkt;
    if (PART && TAIL && blockIdx.z == gridDim.z - 1) NK += ER / BK;
    const int kbase = PART ? blockIdx.z * kch : 0;
    const int m0 = blockIdx.y * BM, n0 = blockIdx.x * BN;
    const int tid  = threadIdx.x;
    const int warp = tid >> 5, wm = warp >> 1, wn = warp & 1;   // 2x2 warps, 64x64
    const int lane = tid & 31, grp = lane >> 2, tig = lane & 3;
    const int lr = tid >> 3, lc = tid & 7;                       // loader: 16 rows x 8 chunks

    float acc[4][8][4];
    #pragma unroll
    for (int i = 0; i < 4; i++)
        #pragma unroll
        for (int j = 0; j < 8; j++)
            #pragma unroll
            for (int c = 0; c < 4; c++) acc[i][j][c] = 0.f;

    const uint32_t sA = (uint32_t)__cvta_generic_to_shared(smem);
    const uint32_t sB = sA + NS * TILEB;

    // ldmatrix per-lane base addresses (stage 0)
    const int l7 = lane & 7, lb = (lane >> 3) & 1, lh = lane >> 4;
    const uint32_t lmA = sA + (uint32_t)((wm * 64 + l7 + lb * 8) * ROWB + lh * 16);
    const uint32_t lmB = sB + (uint32_t)((wn * 64 + l7 + lh * 8) * ROWB + lb * 16);

    // precomputed loader bases (main path)
    const __half* gA0 = A0 + (size_t)(m0 + lr) * K0 + kbase + lc * 8;
    const __half* gB0 = W  + (size_t)(n0 + lr) * K0 + kbase + lc * 8;
    const uint32_t dA0 = sA + (uint32_t)(lr * ROWB + lc * 16);
    const uint32_t dB0 = sB + (uint32_t)(lr * ROWB + lc * 16);

    auto load_tiles = [&](int kt, int buf) {
        if (!TAIL || kbase + kt * BK < K0) {
            const __half* gA = gA0 + kt * BK;
            const __half* gB = gB0 + kt * BK;
            uint32_t dA = dA0 + buf * TILEB;
            uint32_t dB = dB0 + buf * TILEB;
            #pragma unroll
            for (int p = 0; p < 8; p++) {
                cp16(dA + p * (16 * ROWB), gA + (size_t)p * 16 * K0);
                cp16(dB + p * (16 * ROWB), gB + (size_t)p * 16 * K0);
            }
        } else {
            int j = kbase + kt * BK + lc * 8 - K0;   // 0..127: e=j>>4, r=j&15
            #pragma unroll
            for (int p = 0; p < 8; p++) {
                int row = lr + p * 16;
                cp16(dA0 + buf * TILEB + p * (16 * ROWB),
                     AL + (size_t)(m0 + row) * ER + j);
                cp16(dB0 + buf * TILEB + p * (16 * ROWB),
                     BL + ((size_t)(j >> 4) * Nsz + (n0 + row)) * RRK + (j & 15));
            }
        }
    };

    load_tiles(0, 0);
    asm volatile("cp.async.commit_group;");
    load_tiles(1, 1);
    asm volatile("cp.async.commit_group;");

    int s = 0;
    for (int kt = 0; kt < NK; ++kt) {
        asm volatile("cp.async.wait_group 1;");
        __syncthreads();

        if (kt + 2 < NK) load_tiles(kt + 2, (kt + 2) % NS);
        asm volatile("cp.async.commit_group;");

        const uint32_t stA = lmA + s * TILEB;
        const uint32_t stB = lmB + s * TILEB;

        uint32_t af[2][4][4], bf[2][4][4];
        // preload k16 slice 0
        #pragma unroll
        for (int i = 0; i < 4; i++) LDSM4(af[0][i], stA + i * (16 * ROWB));
        #pragma unroll
        for (int p = 0; p < 4; p++) LDSM4(bf[0][p], stB + p * (16 * ROWB));

        #pragma unroll
        for (int s2 = 0; s2 < 4; s2++) {               // four k16 slices, ping-pong
            int cur = s2 & 1, nxt = cur ^ 1;
            if (s2 < 3) {
                #pragma unroll
                for (int i = 0; i < 4; i++)
                    LDSM4(af[nxt][i], stA + i * (16 * ROWB) + (s2 + 1) * 32);
                #pragma unroll
                for (int p = 0; p < 4; p++)
                    LDSM4(bf[nxt][p], stB + p * (16 * ROWB) + (s2 + 1) * 32);
            }
            #pragma unroll
            for (int i = 0; i < 4; i++)
                #pragma unroll
                for (int p = 0; p < 4; p++) {
                    mma_f16(acc[i][2 * p + 0], af[cur][i], &bf[cur][p][0]);
                    mma_f16(acc[i][2 * p + 1], af[cur][i], &bf[cur][p][2]);
                }
        }
        s = (s == NS - 1) ? 0 : s + 1;
    }

    // epilogue
    #pragma unroll
    for (int i = 0; i < 4; i++) {
        int t0 = m0 + wm * 64 + i * 16 + grp;
        #pragma unroll
        for (int j = 0; j < 8; j++) {
            int n = n0 + wn * 64 + j * 8 + 2 * tig;
            if (PART) {
                float* C = (float*)Cout + (size_t)blockIdx.z * TT * Nsz;
                float2 v0 = {acc[i][j][0], acc[i][j][1]};
                float2 v1 = {acc[i][j][2], acc[i][j][3]};
                *reinterpret_cast<float2*>(&C[(size_t)t0 * Nsz + n]) = v0;
                *reinterpret_cast<float2*>(&C[(size_t)(t0 + 8) * Nsz + n]) = v1;
            } else if (GELU) {
                __half2* C = (__half2*)Cout;
                float bv0 = bias[n], bv1 = bias[n + 1];
                C[((size_t)t0 * Nsz + n) >> 1] = __floats2half2_rn(
                    gelu_new_f(acc[i][j][0] + bv0), gelu_new_f(acc[i][j][1] + bv1));
                C[((size_t)(t0 + 8) * Nsz + n) >> 1] = __floats2half2_rn(
                    gelu_new_f(acc[i][j][2] + bv0), gelu_new_f(acc[i][j][3] + bv1));
            } else {
                float* C = (float*)Cout;
                float bv0 = bias[n], bv1 = bias[n + 1];
                float2 v0 = {acc[i][j][0] + bv0, acc[i][j][1] + bv1};
                float2 v1 = {acc[i][j][2] + bv0, acc[i][j][3] + bv1};
                *reinterpret_cast<float2*>(&C[(size_t)t0 * Nsz + n]) = v0;
                *reinterpret_cast<float2*>(&C[(size_t)(t0 + 8) * Nsz + n]) = v1;
            }
        }
    }
}

// ---------------- launch --------------------------------------------------------
extern "C" void kernel_launch(void* const* d_in, const int* in_sizes, int n_in,
                              void* d_out, int out_size) {
    const float* x  = (const float*)d_in[0];
    const int*   ei = (const int*)  d_in[1];
    const float* W1 = (const float*)d_in[2];
    const float* b1 = (const float*)d_in[3];
    const float* A1 = (const float*)d_in[4];
    const float* B1 = (const float*)d_in[5];
    const float* W2 = (const float*)d_in[6];
    const float* b2 = (const float*)d_in[7];
    const float* A2 = (const float*)d_in[8];
    const float* B2 = (const float*)d_in[9];
    float* out = (float*)d_out;

    __half *pW1, *pW2, *pB1, *pB2, *pA1, *pA2, *pX, *pY, *pZ1, *pZ2;
    float* pP;
    cudaGetSymbolAddress((void**)&pW1, g_W1h);
    cudaGetSymbolAddress((void**)&pW2, g_W2h);
    cudaGetSymbolAddress((void**)&pB1, g_B1h);
    cudaGetSymbolAddress((void**)&pB2, g_B2h);
    cudaGetSymbolAddress((void**)&pA1, g_A1h);
    cudaGetSymbolAddress((void**)&pA2, g_A2h);
    cudaGetSymbolAddress((void**)&pX,  g_Xh);
    cudaGetSymbolAddress((void**)&pY,  g_Yh);
    cudaGetSymbolAddress((void**)&pZ1, g_Z1h);
    cudaGetSymbolAddress((void**)&pZ2, g_Z2h);
    cudaGetSymbolAddress((void**)&pP,  g_part);

    cudaFuncSetAttribute(moe_gemm_h<DD, true,  true,  false>,
                         cudaFuncAttributeMaxDynamicSharedMemorySize, SMEMSZ);
    cudaFuncSetAttribute(moe_gemm_h<HH, true,  false, true>,
                         cudaFuncAttributeMaxDynamicSharedMemorySize, SMEMSZ);
    cudaFuncSetAttribute(moe_gemm_h<DD, false, false, true>,
                         cudaFuncAttributeMaxDynamicSharedMemorySize, SMEMSZ);
    cudaFuncSetAttribute(moe_gemm_h<HH, false, false, true>,
                         cudaFuncAttributeMaxDynamicSharedMemorySize, SMEMSZ);

    // one merged conversion for all 7 tensors
    ConvSeg s0 = {(const float4*)W1, (__half2*)pW1, HH * DD / 4};
    ConvSeg s1 = {(const float4*)W2, (__half2*)pW2, DD * HH / 4};
    ConvSeg s2 = {(const float4*)x,  (__half2*)pX,  TT * DD / 4};
    ConvSeg s3 = {(const float4*)B1, (__half2*)pB1, NE * HH * RRK / 4};
    ConvSeg s4 = {(const float4*)B2, (__half2*)pB2, NE * DD * RRK / 4};
    ConvSeg s5 = {(const float4*)A1, (__half2*)pA1, ER * DD / 4};
    ConvSeg s6 = {(const float4*)A2, (__half2*)pA2, ER * HH / 4};
    int total4 = s0.n4 + s1.n4 + s2.n4 + s3.n4 + s4.n4 + s5.n4 + s6.n4;
    tohalf_all_k<<<2048, 256>>>(s0, s1, s2, s3, s4, s5, s6, total4);

    // Z1 partials: split-K over K=2048 (4 chunks of 512)
    moe_gemm_h<DD, false, false, true><<<dim3(1, TT / BM, SPLIT1), NTHR, SMEMSZ>>>(
        pX, nullptr, pA1, nullptr, nullptr, pP, ER, (DD / SPLIT1) / BK, DD / SPLIT1);
    zreduce_k<SPLIT1><<<TT * ER / 256, 256>>>(pP, ei, pZ1);

    // fc1: Y = half(gelu(X@W1^T + b1 + Z1@B1^T))
    moe_gemm_h<DD, true, true, false><<<dim3(HH / BN, TT / BM), NTHR, SMEMSZ>>>(
        pX, pZ1, pW1, pB1, b1, pY, HH, (DD + ER) / BK, 0);

    // Z2 partials: split-K over K=8192 (8 chunks of 1024)
    moe_gemm_h<HH, false, false, true><<<dim3(1, TT / BM, SPLIT2), NTHR, SMEMSZ>>>(
        pY, nullptr, pA2, nullptr, nullptr, pP, ER, (HH / SPLIT2) / BK, HH / SPLIT2);
    zreduce_k<SPLIT2><<<TT * ER / 256, 256>>>(pP, ei, pZ2);

    // fc2 partials: split-K=4 over K=8192 (+ LoRA tail on z=3)
    moe_gemm_h<HH, true, false, true><<<dim3(DD / BN, TT / BM, SPLITF), NTHR, SMEMSZ>>>(
        pY, pZ2, pW2, pB2, nullptr, pP, DD, (HH / SPLITF) / BK, HH / SPLITF);

    // out = sum partials + b2
    oreduce_k<<<TT * DD / 4 / 256, 256>>>(pP, b2, out);
}